// round 1
// baseline (speedup 1.0000x reference)
#include <cuda_runtime.h>
#include <cuda_bf16.h>

// ---------------- problem constants ----------------
#define Bsz 256
#define Nn  2304
#define Cc  10
#define Dd  16
#define Oo  160          // Cc*Dd
#define Ii  8

#define K1_BT 16                 // batches per GEMM block
#define K1_NC 32                 // n per GEMM block
#define K1_CH (Nn / K1_NC)       // 72 chunks (pass-1 partials)
#define K2_NC 36                 // n per routing warp
#define K2_CH (Nn / K2_NC)       // 64 chunks (pass-2/3 partials)
#define PSTR  K1_CH              // partial-buffer chunk stride (max of 72,64)

// ---------------- scratch (static device globals; no runtime alloc) ----------
__device__ float g_uhat[(size_t)Bsz * Nn * Oo];      // 377 MB fp32
__device__ float g_P[(size_t)Bsz * PSTR * Oo];       // partial s sums
__device__ float g_s0[Bsz * Oo];                     // s0
__device__ float g_s01[Bsz * Oo];                    // s0 + s1  (for b2 dot)

// ============ K1: u_hat[b,n,o] = sum_i x[b,n,i] * W[n,i,o]; + partial s0 ====
__global__ __launch_bounds__(160) void k1_gemm(const float* __restrict__ x,
                                               const float* __restrict__ W)
{
    __shared__ float xs[K1_BT][K1_NC][Ii];
    const int b0    = blockIdx.x * K1_BT;
    const int n0    = blockIdx.y * K1_NC;
    const int chunk = blockIdx.y;
    const int tid   = threadIdx.x;

    // cooperative load of x tile: [16 b][32 n][8 i]
    for (int idx = tid; idx < K1_BT * K1_NC * Ii; idx += 160) {
        int bb = idx >> 8;          // / (32*8)
        int r  = idx & 255;
        int nn = r >> 3;
        int i  = r & 7;
        xs[bb][nn][i] = x[((b0 + bb) * Nn + (n0 + nn)) * Ii + i];
    }
    __syncthreads();

    const int o = tid;              // 0..159
    float acc[K1_BT];
#pragma unroll
    for (int bb = 0; bb < K1_BT; bb++) acc[bb] = 0.f;

    for (int nn = 0; nn < K1_NC; nn++) {
        const int n = n0 + nn;
        float w[Ii];
#pragma unroll
        for (int i = 0; i < Ii; i++) w[i] = W[(n * Ii + i) * Oo + o];   // coalesced
#pragma unroll
        for (int bb = 0; bb < K1_BT; bb++) {
            float u = 0.f;
#pragma unroll
            for (int i = 0; i < Ii; i++) u = fmaf(xs[bb][nn][i], w[i], u);
            g_uhat[(size_t)((b0 + bb) * Nn + n) * Oo + o] = u;          // coalesced
            acc[bb] += u;                                               // fixed order
        }
    }
#pragma unroll
    for (int bb = 0; bb < K1_BT; bb++)
        g_P[(size_t)((b0 + bb) * PSTR + chunk) * Oo + o] = acc[bb];
}

// ============ R0: s0 = 0.1 * sum_n u_hat + 0.1  (deterministic chunk order) ==
__global__ void k_r0(void)
{
    int idx = blockIdx.x * blockDim.x + threadIdx.x;     // 40960 threads
    if (idx >= Bsz * Oo) return;
    int b = idx / Oo, o = idx - b * Oo;
    float s = 0.f;
    for (int ch = 0; ch < K1_CH; ch++)
        s += g_P[(size_t)(b * PSTR + ch) * Oo + o];
    g_s0[idx] = 0.1f * s + 0.1f;
}

// ============ routing pass: logits -> softmax -> weighted partial sums =======
// warp per (b, chunk of 36 n). lane owns o = lane + 32k (k<5) => c = 2k + (lane>>4).
// All reductions warp-local (16-lane butterfly + xor16 exchange). No syncthreads.
__global__ __launch_bounds__(256) void k_route(int use_s01)
{
    const int wg   = (blockIdx.x << 3) + (threadIdx.x >> 5);   // 16384 warps
    const int lane = threadIdx.x & 31;
    const int b    = wg >> 6;      // /64 chunks
    const int ch   = wg & 63;
    const int n0   = ch * K2_NC;
    const int h    = lane >> 4;

    const float* sv = use_s01 ? g_s01 : g_s0;
    float sr[5], acc[5];
#pragma unroll
    for (int k = 0; k < 5; k++) {
        sr[k]  = sv[b * Oo + lane + 32 * k];
        acc[k] = 0.f;
    }

    size_t base = (size_t)(b * Nn + n0) * Oo + lane;
    for (int nn = 0; nn < K2_NC; nn++, base += Oo) {
        float u[5], p[5];
#pragma unroll
        for (int k = 0; k < 5; k++) u[k] = g_uhat[base + 32 * k];   // 5x 128B/warp
#pragma unroll
        for (int k = 0; k < 5; k++) p[k] = u[k] * sr[k];
        // sum over d=16 within each 16-lane group -> logit for c = 2k+h
#pragma unroll
        for (int k = 0; k < 5; k++) {
#pragma unroll
            for (int off = 8; off >= 1; off >>= 1)
                p[k] += __shfl_xor_sync(0xffffffffu, p[k], off);
        }
        float q[5];                  // logits for c = 2k + (1-h) from other half
#pragma unroll
        for (int k = 0; k < 5; k++) q[k] = __shfl_xor_sync(0xffffffffu, p[k], 16);

        // stable softmax over the 10 logits
        float m = p[0];
#pragma unroll
        for (int k = 1; k < 5; k++) m = fmaxf(m, p[k]);
#pragma unroll
        for (int k = 0; k < 5; k++) m = fmaxf(m, q[k]);
        float e[5], sum = 0.f;
#pragma unroll
        for (int k = 0; k < 5; k++) {
            e[k]     = __expf(p[k] - m);     // own c = 2k+h
            float eq = __expf(q[k] - m);     // other c = 2k+1-h
            sum += h ? (eq + e[k]) : (e[k] + eq);   // even-c first in both halves
        }
        float inv = 1.0f / sum;
#pragma unroll
        for (int k = 0; k < 5; k++)
            acc[k] = fmaf(e[k] * inv, u[k], acc[k]);   // s partial, fixed n-order
    }
#pragma unroll
    for (int k = 0; k < 5; k++)
        g_P[(size_t)(b * PSTR + ch) * Oo + lane + 32 * k] = acc[k];
}

// ============ R1: s1 = sum + 0.1 ; s01 = s0 + s1 =============================
__global__ void k_r1(void)
{
    int idx = blockIdx.x * blockDim.x + threadIdx.x;
    if (idx >= Bsz * Oo) return;
    int b = idx / Oo, o = idx - b * Oo;
    float s = 0.f;
    for (int ch = 0; ch < K2_CH; ch++)
        s += g_P[(size_t)(b * PSTR + ch) * Oo + o];
    g_s01[idx] = g_s0[idx] + (s + 0.1f);
}

// ============ R2: s2 = sum + 0.1 ; v = squash(s2) ============================
// warp per (b,c); lanes 0..15 = d
__global__ __launch_bounds__(256) void k_r2_squash(float* __restrict__ out)
{
    const int wg   = (blockIdx.x << 3) + (threadIdx.x >> 5);   // 2560 warps
    const int lane = threadIdx.x & 31;
    const int b = wg / Cc;
    const int c = wg - b * Cc;
    float s = 0.f;
    if (lane < Dd) {
        for (int ch = 0; ch < K2_CH; ch++)
            s += g_P[(size_t)(b * PSTR + ch) * Oo + c * Dd + lane];
        s += 0.1f;
    }
    float t = s * s;
#pragma unroll
    for (int off = 8; off >= 1; off >>= 1)
        t += __shfl_xor_sync(0xffffffffu, t, off);   // |s|^2 within 16-lane group
    float nrm = sqrtf(t);
    if (lane < Dd)
        out[(b * Cc + c) * Dd + lane] = s * nrm / (1.0f + t);
}

// ============ launch =========================================================
extern "C" void kernel_launch(void* const* d_in, const int* in_sizes, int n_in,
                              void* d_out, int out_size)
{
    const float* x = (const float*)d_in[0];   // [256,2304,8]
    const float* W = (const float*)d_in[1];   // [2304,8,160]
    float* out = (float*)d_out;               // [256,10,16]

    dim3 g1(Bsz / K1_BT, K1_CH);              // 16 x 72
    k1_gemm<<<g1, 160>>>(x, W);
    k_r0<<<160, 256>>>();
    k_route<<<2048, 256>>>(0);                // pass 2 (s0 -> c1 -> partial s1)
    k_r1<<<160, 256>>>();
    k_route<<<2048, 256>>>(1);                // pass 3 (s0+s1 -> c2 -> partial s2)
    k_r2_squash<<<320, 256>>>(out);
}

// round 4
// speedup vs baseline: 1.6273x; 1.6273x over previous
#include <cuda_runtime.h>

// ---------------- problem constants ----------------
#define Bsz 256
#define Nn  2304
#define Cc  10
#define Dd  16
#define Oo  160          // Cc*Dd
#define Ii  8

#define K1_BT 16                 // batches per GEMM block
#define K1_NC 32                 // n per GEMM block
#define K1_CH (Nn / K1_NC)       // 72 chunks (pass-1 partials)
#define K2_NC 36                 // n per routing warp
#define K2_CH (Nn / K2_NC)       // 64 chunks (pass-2/3 partials)
#define PSTR  K1_CH              // partial-buffer chunk stride (max of 72,64)

// ---------------- scratch (static device globals; no runtime alloc) ----------
__device__ float g_uhat[(size_t)Bsz * Nn * Oo];      // 377 MB fp32
__device__ float g_P[(size_t)Bsz * PSTR * Oo];       // partial s sums
__device__ float g_s0[Bsz * Oo];                     // s0
__device__ float g_s01[Bsz * Oo];                    // s0 + s1  (for b2 dot)

// ============ K1: u_hat[b,n,o] = sum_i x[b,n,i] * W[n,i,o]; + partial s0 ====
__global__ __launch_bounds__(160) void k1_gemm(const float* __restrict__ x,
                                               const float* __restrict__ W)
{
    __shared__ float xs[K1_BT][K1_NC][Ii];
    const int b0    = blockIdx.x * K1_BT;
    const int n0    = blockIdx.y * K1_NC;
    const int chunk = blockIdx.y;
    const int tid   = threadIdx.x;

    // cooperative load of x tile: [16 b][32 n][8 i]
    for (int idx = tid; idx < K1_BT * K1_NC * Ii; idx += 160) {
        int bb = idx >> 8;
        int r  = idx & 255;
        int nn = r >> 3;
        int i  = r & 7;
        xs[bb][nn][i] = x[((b0 + bb) * Nn + (n0 + nn)) * Ii + i];
    }
    __syncthreads();

    const int o = tid;              // 0..159
    float acc[K1_BT];
#pragma unroll
    for (int bb = 0; bb < K1_BT; bb++) acc[bb] = 0.f;

    for (int nn = 0; nn < K1_NC; nn++) {
        const int n = n0 + nn;
        float w[Ii];
#pragma unroll
        for (int i = 0; i < Ii; i++) w[i] = W[(n * Ii + i) * Oo + o];   // coalesced
#pragma unroll
        for (int bb = 0; bb < K1_BT; bb++) {
            float u = 0.f;
#pragma unroll
            for (int i = 0; i < Ii; i++) u = fmaf(xs[bb][nn][i], w[i], u);
            __stcs(&g_uhat[(size_t)((b0 + bb) * Nn + n) * Oo + o], u);  // streaming store
            acc[bb] += u;                                               // fixed order fp32
        }
    }
#pragma unroll
    for (int bb = 0; bb < K1_BT; bb++)
        g_P[(size_t)((b0 + bb) * PSTR + chunk) * Oo + o] = acc[bb];
}

// ============ R0: s0 = 0.1 * sum_n u_hat + 0.1  (deterministic chunk order) ==
__global__ void k_r0(void)
{
    int idx = blockIdx.x * blockDim.x + threadIdx.x;     // 40960 threads
    if (idx >= Bsz * Oo) return;
    int b = idx / Oo, o = idx - b * Oo;
    float s = 0.f;
#pragma unroll 8
    for (int ch = 0; ch < K1_CH; ch++)
        s += g_P[(size_t)(b * PSTR + ch) * Oo + o];
    g_s0[idx] = 0.1f * s + 0.1f;
}

// ============ routing pass: logits -> softmax -> weighted partial sums =======
// warp per (b, chunk of 36 n). Lane owns float2 slots {lane, lane+32, lane+64(<16)}
// i.e. o-pairs (2s, 2s+1). 8-lane slot group holds one c's 16 d's (2 d's per lane).
// Logit reduce: 3-round butterfly x 3 regs; softmax assembled via xor8 + xor16.
__global__ __launch_bounds__(256) void k_route(int use_s01)
{
    const int wg   = (blockIdx.x << 3) + (threadIdx.x >> 5);   // 16384 warps
    const int lane = threadIdx.x & 31;
    const int b    = wg >> 6;      // /64 chunks
    const int ch   = wg & 63;
    const int n0   = ch * K2_NC;
    const bool j2v = (lane < 16);

    const float2* sv = (const float2*)((use_s01 ? g_s01 : g_s0) + b * Oo);
    float2 sr0 = sv[lane];
    float2 sr1 = sv[lane + 32];
    float2 sr2 = make_float2(0.f, 0.f);
    if (j2v) sr2 = sv[lane + 64];

    float2 a0 = make_float2(0.f, 0.f);
    float2 a1 = make_float2(0.f, 0.f);
    float2 a2 = make_float2(0.f, 0.f);

    const float2* up = (const float2*)g_uhat
                       + ((size_t)(b * Nn + n0) * Oo >> 1) + lane;
    for (int nn = 0; nn < K2_NC; nn++, up += (Oo >> 1)) {
        float2 u0 = __ldcs(&up[0]);       // streaming reads, 256B/warp each
        float2 u1 = __ldcs(&up[32]);
        float2 u2 = make_float2(0.f, 0.f);
        if (j2v) u2 = __ldcs(&up[64]);

        // per-lane 2-d partial logits
        float p0 = fmaf(u0.y, sr0.y, u0.x * sr0.x);
        float p1 = fmaf(u1.y, sr1.y, u1.x * sr1.x);
        float p2 = fmaf(u2.y, sr2.y, u2.x * sr2.x);
        // reduce over the 8-lane d-group
#pragma unroll
        for (int off = 1; off <= 4; off <<= 1) {
            p0 += __shfl_xor_sync(0xffffffffu, p0, off);
            p1 += __shfl_xor_sync(0xffffffffu, p1, off);
            p2 += __shfl_xor_sync(0xffffffffu, p2, off);
        }
        if (!j2v) p2 = -1e30f;     // lanes 16..31 hold no j2 class

        // global max over the 10 logits (4 groups x 3 each, masked)
        float m = fmaxf(fmaxf(p0, p1), p2);
        m = fmaxf(m, __shfl_xor_sync(0xffffffffu, m, 8));
        m = fmaxf(m, __shfl_xor_sync(0xffffffffu, m, 16));

        float e0 = __expf(p0 - m);
        float e1 = __expf(p1 - m);
        float e2 = __expf(p2 - m);  // 0 for masked lanes
        float s  = e0 + e1 + e2;
        s += __shfl_xor_sync(0xffffffffu, s, 8);
        s += __shfl_xor_sync(0xffffffffu, s, 16);   // sum over all 10
        float inv = __fdividef(1.f, s);

        float w0 = e0 * inv, w1 = e1 * inv, w2 = e2 * inv;
        a0.x = fmaf(w0, u0.x, a0.x);  a0.y = fmaf(w0, u0.y, a0.y);
        a1.x = fmaf(w1, u1.x, a1.x);  a1.y = fmaf(w1, u1.y, a1.y);
        a2.x = fmaf(w2, u2.x, a2.x);  a2.y = fmaf(w2, u2.y, a2.y);
    }

    float2* P = (float2*)(g_P + (size_t)(b * PSTR + ch) * Oo);
    P[lane]      = a0;
    P[lane + 32] = a1;
    if (j2v) P[lane + 64] = a2;
}

// ============ R1: s1 = sum + 0.1 ; s01 = s0 + s1 =============================
__global__ void k_r1(void)
{
    int idx = blockIdx.x * blockDim.x + threadIdx.x;
    if (idx >= Bsz * Oo) return;
    int b = idx / Oo, o = idx - b * Oo;
    float s = 0.f;
#pragma unroll 8
    for (int ch = 0; ch < K2_CH; ch++)
        s += g_P[(size_t)(b * PSTR + ch) * Oo + o];
    g_s01[idx] = g_s0[idx] + (s + 0.1f);
}

// ============ R2: s2 = sum + 0.1 ; v = squash(s2) ============================
// warp per (b,c); lanes 0..15 = d
__global__ __launch_bounds__(256) void k_r2_squash(float* __restrict__ out)
{
    const int wg   = (blockIdx.x << 3) + (threadIdx.x >> 5);   // 2560 warps
    const int lane = threadIdx.x & 31;
    const int b = wg / Cc;
    const int c = wg - b * Cc;
    float s = 0.f;
    if (lane < Dd) {
#pragma unroll 8
        for (int ch = 0; ch < K2_CH; ch++)
            s += g_P[(size_t)(b * PSTR + ch) * Oo + c * Dd + lane];
        s += 0.1f;
    }
    float t = s * s;
#pragma unroll
    for (int off = 8; off >= 1; off >>= 1)
        t += __shfl_xor_sync(0xffffffffu, t, off);   // |s|^2 within 16-lane group
    float nrm = sqrtf(t);
    if (lane < Dd)
        out[(b * Cc + c) * Dd + lane] = s * nrm / (1.0f + t);
}

// ============ launch =========================================================
extern "C" void kernel_launch(void* const* d_in, const int* in_sizes, int n_in,
                              void* d_out, int out_size)
{
    const float* x = (const float*)d_in[0];   // [256,2304,8]
    const float* W = (const float*)d_in[1];   // [2304,8,160]
    float* out = (float*)d_out;               // [256,10,16]

    dim3 g1(Bsz / K1_BT, K1_CH);              // 16 x 72
    k1_gemm<<<g1, 160>>>(x, W);
    k_r0<<<160, 256>>>();
    k_route<<<2048, 256>>>(0);                // pass 2 (s0 -> c1 -> partial s1)
    k_r1<<<160, 256>>>();
    k_route<<<2048, 256>>>(1);                // pass 3 (s0+s1 -> c2 -> partial s2)
    k_r2_squash<<<320, 256>>>(out);
}